// round 14
// baseline (speedup 1.0000x reference)
#include <cuda_runtime.h>
#include <math.h>

#define PI_F 3.14159265358979323846f

// ---- float4 helpers ----
__device__ __forceinline__ float4 operator+(float4 a, float4 b){ return make_float4(a.x+b.x,a.y+b.y,a.z+b.z,a.w+b.w); }
__device__ __forceinline__ float4 operator-(float4 a, float4 b){ return make_float4(a.x-b.x,a.y-b.y,a.z-b.z,a.w-b.w); }
__device__ __forceinline__ float4 operator*(float4 a, float s){ return make_float4(a.x*s,a.y*s,a.z*s,a.w*s); }
__device__ __forceinline__ void operator+=(float4& a, float4 b){ a.x+=b.x; a.y+=b.y; a.z+=b.z; a.w+=b.w; }
__device__ __forceinline__ void operator-=(float4& a, float4 b){ a.x-=b.x; a.y-=b.y; a.z-=b.z; a.w-=b.w; }

// ---------------- scratch ----------------
__device__ float g_Fer[64*64*64];    // parity-folded F: [m][t<64][c]
__device__ float g_Fei[64*64*64];
__device__ float g_For[64*64*64];
__device__ float g_Foi[64*64*64];
__device__ float g_flmr[64*64*64];   // [l][m][c]
__device__ float g_flmi[64*64*64];
__device__ float g_glr[64*127*64];   // [l][mf][o]
__device__ float g_gli[64*127*64];
__device__ float g_gr[128*127*64];   // [t][mf][o]
__device__ float g_gi[128*127*64];
__device__ float g_cE[127*128];      // [mf][k]
__device__ float g_sE[127*128];
__device__ float g_tv[64];
__device__ float g_bt[64];
__device__ float g_cw[64];
__device__ float g_cb[1];

// ---------------- setup: E twiddle table + time modulation ---------------
__global__ void k_setup(const float* __restrict__ t_emb,
                        const float* __restrict__ dense_w,
                        const float* __restrict__ conv_w,
                        const float* __restrict__ conv_b,
                        const float* __restrict__ time_w) {
    int bx = blockIdx.x;
    int tid = threadIdx.x;              // 256
    const float w0 = 2.0f * PI_F / 128.0f;
    if (bx < 64) {                      // E table [mf][k], 127*128
        int j = bx*256 + tid;
        if (j < 127*128) {
            int mf = j >> 7, k = j & 127;
            int m = mf - 63;
            int r = ((m * k) % 128 + 128) & 127;
            float s, c; sincosf(w0 * (float)r, &s, &c);
            g_cE[mf*128 + k] = c; g_sE[mf*128 + k] = s;
        }
    } else {                            // time modulation
        __shared__ float psum[256];
        __shared__ float psi[128];
        int j = tid >> 1, half = tid & 1;
        float s = 0.f;
        const float* dw = dense_w + half*128*128 + j;
        #pragma unroll 8
        for (int d = 0; d < 128; d++) s += t_emb[half*128 + d] * dw[d*128];
        psum[tid] = s;
        __syncthreads();
        if (tid < 128) psi[tid] = psum[2*tid] + psum[2*tid + 1];
        __syncthreads();
        if (tid < 64) {
            float tv = 0.f;
            for (int jj = 0; jj < 64; jj++) tv += time_w[tid*64 + jj] * psi[jj];
            g_tv[tid] = tv;
            g_bt[tid] = psi[64 + tid];
        } else if (tid < 128) {
            int c = tid - 64;
            float cs = 0.f;
            for (int o = 0; o < 64; o++) cs += conv_w[c*64 + o];
            g_cw[c] = cs;
        } else if (tid == 128) {
            float cb = 0.f;
            for (int o = 0; o < 64; o++) cb += conv_b[o];
            g_cb[0] = cb;
        }
    }
}

// ---------------- longitude DFT + theta-parity fold (fused) --------------
__global__ void k_dftp(const float* __restrict__ x,
                       const float* __restrict__ quad_w) {
    int tp = blockIdx.x;                // 0..63
    int c0 = blockIdx.y * 32;
    int tid = threadIdx.x;              // 512
    int cq = tid & 7, mg = tid >> 3;    // c = c0 + cq*4, m = mg (0..63)
    const float w0 = 2.0f * PI_F / 128.0f;
    __shared__ float xeA[64*32], xoA[64*32], xeB[64*32], xoB[64*32];
    __shared__ float tcs[16*64], tss[16*64];
    const float* xA = x + tp*8192 + c0;
    const float* xB = x + (127 - tp)*8192 + c0;
    for (int i = tid; i < 64*8; i += 512) {   // 64 n-rows x 8 float4
        int n = i >> 3, f = i & 7;
        if (n == 0) {
            ((float4*)xeA)[f] = *(const float4*)(xA + f*4);          // x[0]
            ((float4*)xoA)[f] = *(const float4*)(xA + 64*64 + f*4);  // x[64]
            ((float4*)xeB)[f] = *(const float4*)(xB + f*4);
            ((float4*)xoB)[f] = *(const float4*)(xB + 64*64 + f*4);
        } else {
            float4 a = *(const float4*)(xA + n*64 + f*4);
            float4 b = *(const float4*)(xA + (128 - n)*64 + f*4);
            ((float4*)xeA)[i] = a + b;
            ((float4*)xoA)[i] = a - b;
            a = *(const float4*)(xB + n*64 + f*4);
            b = *(const float4*)(xB + (128 - n)*64 + f*4);
            ((float4*)xeB)[i] = a + b;
            ((float4*)xoB)[i] = a - b;
        }
    }
    float4 arA = {0,0,0,0}, aiA = {0,0,0,0}, arB = {0,0,0,0}, aiB = {0,0,0,0};
    for (int ch = 0; ch < 4; ch++) {
        __syncthreads();
        for (int i = tid; i < 1024; i += 512) {   // twiddle chunk [16n][64m]
            int n = ch*16 + (i >> 6), m = i & 63;
            int r = (m * n) & 127;
            float s, c; sincosf(w0 * (float)r, &s, &c);
            tcs[i] = c; tss[i] = s;
        }
        __syncthreads();
        #pragma unroll 4
        for (int ln = 0; ln < 16; ln++) {
            int n = ch*16 + ln;
            if (n == 0) continue;
            float4 xeAv = ((float4*)xeA)[n*8 + cq];
            float4 xoAv = ((float4*)xoA)[n*8 + cq];
            float4 xeBv = ((float4*)xeB)[n*8 + cq];
            float4 xoBv = ((float4*)xoB)[n*8 + cq];
            float cv = tcs[ln*64 + mg];
            float sv = tss[ln*64 + mg];
            arA += xeAv * cv;  aiA -= xoAv * sv;
            arB += xeBv * cv;  aiB -= xoBv * sv;
        }
    }
    float sgn = (mg & 1) ? -1.f : 1.f;
    float4 x0A  = ((float4*)xeA)[cq], x64A = ((float4*)xoA)[cq];
    float4 x0B  = ((float4*)xeB)[cq], x64B = ((float4*)xoB)[cq];
    arA += x0A + x64A * sgn;
    arB += x0B + x64B * sgn;
    float sA = (2.0f * PI_F / 128.0f) * quad_w[tp];
    float sB = (2.0f * PI_F / 128.0f) * quad_w[127 - tp];
    float4 FrA = arA * sA, FiA = aiA * sA;
    float4 FrB = arB * sB, FiB = aiB * sB;
    int off = (mg*64 + tp)*64 + c0 + cq*4;
    *(float4*)(g_Fer + off) = FrA + FrB;
    *(float4*)(g_For + off) = FrA - FrB;
    *(float4*)(g_Fei + off) = FiA + FiB;
    *(float4*)(g_Foi + off) = FiA - FiB;
}

// ---------------- Legendre analysis (parity-halved) ----------------------
__global__ void k_ana(const float* __restrict__ P_in) {
    int m = blockIdx.x, l0 = blockIdx.y * 16;
    int tid = threadIdx.x;              // 256
    int cq = tid & 15, li = tid >> 4;
    int l = l0 + li;
    __shared__ float Ps[16*64];         // [li][t<64]
    for (int i = tid; i < 16*16; i += 256)
        ((float4*)Ps)[i] = *(const float4*)(P_in + (size_t)((l0 + (i >> 4))*127 + 63 + m)*128 + (i & 15)*4);
    __syncthreads();
    int p = (l + m) & 1;
    const float4* Fr4 = (const float4*)((p ? g_For : g_Fer) + m*4096);
    const float4* Fi4 = (const float4*)((p ? g_Foi : g_Fei) + m*4096);
    float4 ar = {0,0,0,0}, ai = {0,0,0,0};
    #pragma unroll 4
    for (int tt = 0; tt < 64; tt++) {
        float pv = Ps[li*64 + tt];
        float4 fr = Fr4[tt*16 + cq];
        float4 fi = Fi4[tt*16 + cq];
        ar += fr * pv;
        ai += fi * pv;
    }
    *(float4*)(g_flmr + (l*64 + m)*64 + cq*4) = ar;
    *(float4*)(g_flmi + (l*64 + m)*64 + cq*4) = ai;
}

// ---------------- complex spectral weight multiply (266 MB stream) -------
// Round-8 structure (measured best): 2 l per block, grid 127x32,
// 16 independent LDG.128 per thread, two-phase smem reduction.
__global__ void k_wmul(const float* __restrict__ wr,
                       const float* __restrict__ wi) {
    int mf = blockIdx.x, l0 = blockIdx.y * 2;
    int tid = threadIdx.x;              // 256
    int og = tid & 15;
    int ig = tid >> 4;
    __shared__ float ar[2][64], ai[2][64];
    __shared__ float red[4][16][64];    // gr0, gi0, gr1, gi1
    if (tid < 128) {
        int ll = tid >> 6, i = tid & 63;
        int l = l0 + ll;
        float r, im;
        if (mf >= 63) {
            int m = mf - 63;
            r  = g_flmr[(l*64 + m)*64 + i];
            im = g_flmi[(l*64 + m)*64 + i];
        } else {
            int m = 63 - mf;
            float sgn = (m & 1) ? -1.f : 1.f;
            r  =  sgn * g_flmr[(l*64 + m)*64 + i];
            im = -sgn * g_flmi[(l*64 + m)*64 + i];
        }
        ar[ll][i] = r; ai[ll][i] = im;
    }
    __syncthreads();
    const float4* wr0 = (const float4*)(wr + (size_t)(l0*127 + mf)*4096);
    const float4* wi0 = (const float4*)(wi + (size_t)(l0*127 + mf)*4096);
    const float4* wr1 = (const float4*)(wr + (size_t)((l0+1)*127 + mf)*4096);
    const float4* wi1 = (const float4*)(wi + (size_t)((l0+1)*127 + mf)*4096);
    float4 gr0 = {0,0,0,0}, gi0 = {0,0,0,0}, gr1 = {0,0,0,0}, gi1 = {0,0,0,0};
    #pragma unroll
    for (int ii = 0; ii < 4; ii++) {
        int i = ig*4 + ii;
        float4 a0 = wr0[i*16 + og];
        float4 b0 = wi0[i*16 + og];
        float4 a1 = wr1[i*16 + og];
        float4 b1 = wi1[i*16 + og];
        float xr0 = ar[0][i], xi0 = ai[0][i];
        float xr1 = ar[1][i], xi1 = ai[1][i];
        gr0 += a0 * xr0;  gr0 -= b0 * xi0;
        gi0 += b0 * xr0;  gi0 += a0 * xi0;
        gr1 += a1 * xr1;  gr1 -= b1 * xi1;
        gi1 += b1 * xr1;  gi1 += a1 * xi1;
    }
    *(float4*)&red[0][ig][og*4] = gr0;
    *(float4*)&red[1][ig][og*4] = gi0;
    *(float4*)&red[2][ig][og*4] = gr1;
    *(float4*)&red[3][ig][og*4] = gi1;
    __syncthreads();
    if (tid < 128) {
        int ll = tid >> 6, o = tid & 63;
        float sr = 0.f, si = 0.f;
        #pragma unroll
        for (int g = 0; g < 16; g++) {
            sr += red[ll*2 + 0][g][o];
            si += red[ll*2 + 1][g][o];
        }
        g_glr[((l0 + ll)*127 + mf)*64 + o] = sr;
        g_gli[((l0 + ll)*127 + mf)*64 + o] = si;
    }
}

// ---------------- Legendre synthesis (theta-parity folded) ---------------
// Unsplit (round-10 staging), but 512 threads: 2 t per thread, 16 warps.
__global__ void k_synl(const float* __restrict__ P_out) {
    int mf = blockIdx.x;
    int m = (mf >= 63) ? (mf - 63) : (63 - mf);
    int tid = threadIdx.x;              // 512
    int og = tid & 15, tg = tid >> 4;   // og: o-quad (16), tg: t-pair (32)
    __shared__ float glsr[64*64], glsi[64*64];  // [l][o]
    __shared__ float Ps[64*64];                 // [l][t<64]
    for (int i = tid; i < 64*16; i += 512) {
        int l = i >> 4, f = i & 15;
        ((float4*)glsr)[i] = *(const float4*)(g_glr + (l*127 + mf)*64 + f*4);
        ((float4*)glsi)[i] = *(const float4*)(g_gli + (l*127 + mf)*64 + f*4);
        ((float4*)Ps)[i]   = *(const float4*)(P_out + (size_t)(l*127 + mf)*128 + f*4);
    }
    __syncthreads();
    float4 Ar[2], Ai[2], Br[2], Bi[2];
    #pragma unroll
    for (int j = 0; j < 2; j++) {
        Ar[j] = make_float4(0,0,0,0); Ai[j] = make_float4(0,0,0,0);
        Br[j] = make_float4(0,0,0,0); Bi[j] = make_float4(0,0,0,0);
    }
    int pA = m & 1;
    #pragma unroll 4
    for (int j2 = 0; j2 < 32; j2++) {
        int lA = pA + 2*j2, lB = (pA ^ 1) + 2*j2;
        float4 grA = ((float4*)glsr)[lA*16 + og];
        float4 giA = ((float4*)glsi)[lA*16 + og];
        float2 pAv = *(float2*)&Ps[lA*64 + tg*2];
        float4 grB = ((float4*)glsr)[lB*16 + og];
        float4 giB = ((float4*)glsi)[lB*16 + og];
        float2 pBv = *(float2*)&Ps[lB*64 + tg*2];
        Ar[0] += grA * pAv.x;  Ai[0] += giA * pAv.x;
        Ar[1] += grA * pAv.y;  Ai[1] += giA * pAv.y;
        Br[0] += grB * pBv.x;  Bi[0] += giB * pBv.x;
        Br[1] += grB * pBv.y;  Bi[1] += giB * pBv.y;
    }
    #pragma unroll
    for (int j = 0; j < 2; j++) {
        int t  = tg*2 + j;
        int t2 = 127 - t;
        *(float4*)(g_gr + (t *127 + mf)*64 + og*4) = Ar[j] + Br[j];
        *(float4*)(g_gi + (t *127 + mf)*64 + og*4) = Ai[j] + Bi[j];
        *(float4*)(g_gr + (t2*127 + mf)*64 + og*4) = Ar[j] - Br[j];
        *(float4*)(g_gi + (t2*127 + mf)*64 + og*4) = Ai[j] - Bi[j];
    }
}

// ---------------- fused inverse-longitude + conv + LN + ReLU -------------
// Round-10 form (measured best), unsplit.
__global__ void k_ifin(const float* __restrict__ x,
                       const float* __restrict__ ln_scale,
                       const float* __restrict__ ln_bias,
                       float* __restrict__ out) {
    int t = blockIdx.x;
    int tid = threadIdx.x;              // 320
    int og = tid & 15, kg = tid >> 4;   // kg 0..19; k' = kg*4+j
    bool act = (kg <= 16);
    __shared__ float GrS[8*64], GiS[8*64];
    __shared__ float cS[8*68], sS[8*68];
    __shared__ float xs[128*64];        // x_spec tile
    float4 A[4], B[4];
    #pragma unroll
    for (int j = 0; j < 4; j++) { A[j] = make_float4(0,0,0,0); B[j] = make_float4(0,0,0,0); }
    for (int ch = 0; ch < 8; ch++) {
        int mm0 = ch * 8;
        __syncthreads();
        for (int i = tid; i < 8*16; i += 320) {
            int mm = i >> 4, f = i & 15;
            int MM = mm0 + mm;
            float4 grv = *((const float4*)(g_gr + (t*127 + 63 + MM)*64) + f);
            float4 giv = *((const float4*)(g_gi + (t*127 + 63 + MM)*64) + f);
            if (MM) {
                grv += *((const float4*)(g_gr + (t*127 + 63 - MM)*64) + f);
                giv -= *((const float4*)(g_gi + (t*127 + 63 - MM)*64) + f);
            }
            ((float4*)GrS)[i] = grv;
            ((float4*)GiS)[i] = giv;
        }
        for (int i = tid; i < 8*17; i += 320) {
            int mm = i / 17, f = i % 17;
            ((float4*)cS)[i] = *(const float4*)(g_cE + (63 + mm0 + mm)*128 + f*4);
            ((float4*)sS)[i] = *(const float4*)(g_sE + (63 + mm0 + mm)*128 + f*4);
        }
        __syncthreads();
        if (act) {
            #pragma unroll
            for (int mm = 0; mm < 8; mm++) {
                float4 Gr = ((float4*)GrS)[mm*16 + og];
                float4 Gi = ((float4*)GiS)[mm*16 + og];
                float4 cv = *(float4*)&cS[mm*68 + kg*4];
                float4 sv = *(float4*)&sS[mm*68 + kg*4];
                A[0] += Gr * cv.x;  B[0] += Gi * sv.x;
                A[1] += Gr * cv.y;  B[1] += Gi * sv.y;
                A[2] += Gr * cv.z;  B[2] += Gi * sv.z;
                A[3] += Gr * cv.w;  B[3] += Gi * sv.w;
            }
        }
    }
    if (act) {
        #pragma unroll
        for (int j = 0; j < 4; j++) {
            int k = kg*4 + j;
            if (k <= 64) {
                *(float4*)&xs[k*64 + og*4] = A[j] - B[j];
                if (k >= 1 && k <= 63)
                    *(float4*)&xs[(128 - k)*64 + og*4] = A[j] + B[j];
            }
        }
    }
    __syncthreads();
    // ---- phase 2: conv-path scalar + LN + ReLU (first 8 warps) ----
    if (tid < 256) {
        int w = tid >> 5, lane = tid & 31;
        float cw1 = g_cw[lane],        cw2 = g_cw[lane + 32];
        float tv1 = g_tv[lane],        tv2 = g_tv[lane + 32];
        float bt1 = g_bt[lane],        bt2 = g_bt[lane + 32];
        float lns1 = ln_scale[lane],   lnb1 = ln_bias[lane];
        float lns2 = ln_scale[lane+32], lnb2 = ln_bias[lane+32];
        float cb = g_cb[0];
        for (int k = w; k < 128; k += 8) {
            const float* xp = x + (t*128 + k)*64;
            float x1 = xp[lane], x2 = xp[lane + 32];
            float S = x1*cw1 + x2*cw2;
            #pragma unroll
            for (int off = 16; off; off >>= 1)
                S += __shfl_xor_sync(0xffffffffu, S, off);
            S += cb;
            float v1 = xs[k*64 + lane]      + tv1*S + bt1;
            float v2 = xs[k*64 + lane + 32] + tv2*S + bt2;
            float s  = v1 + v2;
            float sq = v1*v1 + v2*v2;
            #pragma unroll
            for (int off = 16; off; off >>= 1) {
                s  += __shfl_xor_sync(0xffffffffu, s,  off);
                sq += __shfl_xor_sync(0xffffffffu, sq, off);
            }
            float mu   = s * (1.0f/64.0f);
            float var  = sq * (1.0f/64.0f) - mu*mu;
            float rstd = rsqrtf(var + 1e-6f);
            float r1 = (v1 - mu)*rstd*lns1 + lnb1;
            float r2 = (v2 - mu)*rstd*lns2 + lnb2;
            float* op = out + (t*128 + k)*64;
            op[lane]      = fmaxf(r1, 0.f);
            op[lane + 32] = fmaxf(r2, 0.f);
        }
    }
}

// ---------------- launch -------------------------------------------------
extern "C" void kernel_launch(void* const* d_in, const int* in_sizes, int n_in,
                              void* d_out, int out_size) {
    const float* x        = (const float*)d_in[0];
    const float* t_emb    = (const float*)d_in[1];
    const float* wr       = (const float*)d_in[2];
    const float* wi       = (const float*)d_in[3];
    const float* conv_w   = (const float*)d_in[4];
    const float* conv_b   = (const float*)d_in[5];
    const float* time_w   = (const float*)d_in[6];
    const float* dense_w  = (const float*)d_in[7];
    const float* ln_scale = (const float*)d_in[8];
    const float* ln_bias  = (const float*)d_in[9];
    const float* P_in     = (const float*)d_in[10];
    const float* P_out    = (const float*)d_in[11];
    const float* quad_w   = (const float*)d_in[12];
    float* out = (float*)d_out;

    k_dftp <<<dim3(64, 2), 512>>>(x, quad_w);
    k_setup<<<65, 256>>>(t_emb, dense_w, conv_w, conv_b, time_w);
    k_ana  <<<dim3(64, 4), 256>>>(P_in);
    k_wmul <<<dim3(127, 32), 256>>>(wr, wi);
    k_synl <<<127, 512>>>(P_out);
    k_ifin <<<128, 320>>>(x, ln_scale, ln_bias, out);
}

// round 15
// speedup vs baseline: 1.1628x; 1.1628x over previous
#include <cuda_runtime.h>
#include <math.h>

#define PI_F 3.14159265358979323846f

// ---- float4 helpers ----
__device__ __forceinline__ float4 operator+(float4 a, float4 b){ return make_float4(a.x+b.x,a.y+b.y,a.z+b.z,a.w+b.w); }
__device__ __forceinline__ float4 operator-(float4 a, float4 b){ return make_float4(a.x-b.x,a.y-b.y,a.z-b.z,a.w-b.w); }
__device__ __forceinline__ float4 operator*(float4 a, float s){ return make_float4(a.x*s,a.y*s,a.z*s,a.w*s); }
__device__ __forceinline__ void operator+=(float4& a, float4 b){ a.x+=b.x; a.y+=b.y; a.z+=b.z; a.w+=b.w; }
__device__ __forceinline__ void operator-=(float4& a, float4 b){ a.x-=b.x; a.y-=b.y; a.z-=b.z; a.w-=b.w; }

// ---------------- scratch ----------------
__device__ float g_Fer[64*64*64];    // parity-folded F: [m][t<64][c]
__device__ float g_Fei[64*64*64];
__device__ float g_For[64*64*64];
__device__ float g_Foi[64*64*64];
__device__ float g_flmr[64*64*64];   // [l][m][c]
__device__ float g_flmi[64*64*64];
__device__ float g_glr[64*127*64];   // [l][mf][o]
__device__ float g_gli[64*127*64];
__device__ float g_gr[128*127*64];   // [t][mf][o]
__device__ float g_gi[128*127*64];
__device__ float g_cE[127*128];      // [mf][k]
__device__ float g_sE[127*128];
__device__ float g_tv[64];
__device__ float g_bt[64];
__device__ float g_cw[64];
__device__ float g_cb[1];

// ---------------- setup: E twiddle table + time modulation ---------------
__global__ void k_setup(const float* __restrict__ t_emb,
                        const float* __restrict__ dense_w,
                        const float* __restrict__ conv_w,
                        const float* __restrict__ conv_b,
                        const float* __restrict__ time_w) {
    int bx = blockIdx.x;
    int tid = threadIdx.x;              // 256
    const float w0 = 2.0f * PI_F / 128.0f;
    if (bx < 64) {                      // E table [mf][k], 127*128
        int j = bx*256 + tid;
        if (j < 127*128) {
            int mf = j >> 7, k = j & 127;
            int m = mf - 63;
            int r = ((m * k) % 128 + 128) & 127;
            float s, c; sincosf(w0 * (float)r, &s, &c);
            g_cE[mf*128 + k] = c; g_sE[mf*128 + k] = s;
        }
    } else {                            // time modulation
        __shared__ float psum[256];
        __shared__ float psi[128];
        int j = tid >> 1, half = tid & 1;
        float s = 0.f;
        const float* dw = dense_w + half*128*128 + j;
        #pragma unroll 8
        for (int d = 0; d < 128; d++) s += t_emb[half*128 + d] * dw[d*128];
        psum[tid] = s;
        __syncthreads();
        if (tid < 128) psi[tid] = psum[2*tid] + psum[2*tid + 1];
        __syncthreads();
        if (tid < 64) {
            float tv = 0.f;
            for (int jj = 0; jj < 64; jj++) tv += time_w[tid*64 + jj] * psi[jj];
            g_tv[tid] = tv;
            g_bt[tid] = psi[64 + tid];
        } else if (tid < 128) {
            int c = tid - 64;
            float cs = 0.f;
            for (int o = 0; o < 64; o++) cs += conv_w[c*64 + o];
            g_cw[c] = cs;
        } else if (tid == 128) {
            float cb = 0.f;
            for (int o = 0; o < 64; o++) cb += conv_b[o];
            g_cb[0] = cb;
        }
    }
}

// ---------------- longitude DFT + theta-parity fold (fused) --------------
__global__ void k_dftp(const float* __restrict__ x,
                       const float* __restrict__ quad_w) {
    int tp = blockIdx.x;                // 0..63
    int c0 = blockIdx.y * 32;
    int tid = threadIdx.x;              // 512
    int cq = tid & 7, mg = tid >> 3;    // c = c0 + cq*4, m = mg (0..63)
    const float w0 = 2.0f * PI_F / 128.0f;
    __shared__ float xeA[64*32], xoA[64*32], xeB[64*32], xoB[64*32];
    __shared__ float tcs[16*64], tss[16*64];
    const float* xA = x + tp*8192 + c0;
    const float* xB = x + (127 - tp)*8192 + c0;
    for (int i = tid; i < 64*8; i += 512) {   // 64 n-rows x 8 float4
        int n = i >> 3, f = i & 7;
        if (n == 0) {
            ((float4*)xeA)[f] = *(const float4*)(xA + f*4);          // x[0]
            ((float4*)xoA)[f] = *(const float4*)(xA + 64*64 + f*4);  // x[64]
            ((float4*)xeB)[f] = *(const float4*)(xB + f*4);
            ((float4*)xoB)[f] = *(const float4*)(xB + 64*64 + f*4);
        } else {
            float4 a = *(const float4*)(xA + n*64 + f*4);
            float4 b = *(const float4*)(xA + (128 - n)*64 + f*4);
            ((float4*)xeA)[i] = a + b;
            ((float4*)xoA)[i] = a - b;
            a = *(const float4*)(xB + n*64 + f*4);
            b = *(const float4*)(xB + (128 - n)*64 + f*4);
            ((float4*)xeB)[i] = a + b;
            ((float4*)xoB)[i] = a - b;
        }
    }
    float4 arA = {0,0,0,0}, aiA = {0,0,0,0}, arB = {0,0,0,0}, aiB = {0,0,0,0};
    for (int ch = 0; ch < 4; ch++) {
        __syncthreads();
        for (int i = tid; i < 1024; i += 512) {   // twiddle chunk [16n][64m]
            int n = ch*16 + (i >> 6), m = i & 63;
            int r = (m * n) & 127;
            float s, c; sincosf(w0 * (float)r, &s, &c);
            tcs[i] = c; tss[i] = s;
        }
        __syncthreads();
        #pragma unroll 4
        for (int ln = 0; ln < 16; ln++) {
            int n = ch*16 + ln;
            if (n == 0) continue;
            float4 xeAv = ((float4*)xeA)[n*8 + cq];
            float4 xoAv = ((float4*)xoA)[n*8 + cq];
            float4 xeBv = ((float4*)xeB)[n*8 + cq];
            float4 xoBv = ((float4*)xoB)[n*8 + cq];
            float cv = tcs[ln*64 + mg];
            float sv = tss[ln*64 + mg];
            arA += xeAv * cv;  aiA -= xoAv * sv;
            arB += xeBv * cv;  aiB -= xoBv * sv;
        }
    }
    float sgn = (mg & 1) ? -1.f : 1.f;
    float4 x0A  = ((float4*)xeA)[cq], x64A = ((float4*)xoA)[cq];
    float4 x0B  = ((float4*)xeB)[cq], x64B = ((float4*)xoB)[cq];
    arA += x0A + x64A * sgn;
    arB += x0B + x64B * sgn;
    float sA = (2.0f * PI_F / 128.0f) * quad_w[tp];
    float sB = (2.0f * PI_F / 128.0f) * quad_w[127 - tp];
    float4 FrA = arA * sA, FiA = aiA * sA;
    float4 FrB = arB * sB, FiB = aiB * sB;
    int off = (mg*64 + tp)*64 + c0 + cq*4;
    *(float4*)(g_Fer + off) = FrA + FrB;
    *(float4*)(g_For + off) = FrA - FrB;
    *(float4*)(g_Fei + off) = FiA + FiB;
    *(float4*)(g_Foi + off) = FiA - FiB;
}

// ---------------- Legendre analysis (parity-halved) ----------------------
__global__ void k_ana(const float* __restrict__ P_in) {
    int m = blockIdx.x, l0 = blockIdx.y * 16;
    int tid = threadIdx.x;              // 256
    int cq = tid & 15, li = tid >> 4;
    int l = l0 + li;
    __shared__ float Ps[16*64];         // [li][t<64]
    for (int i = tid; i < 16*16; i += 256)
        ((float4*)Ps)[i] = *(const float4*)(P_in + (size_t)((l0 + (i >> 4))*127 + 63 + m)*128 + (i & 15)*4);
    __syncthreads();
    int p = (l + m) & 1;
    const float4* Fr4 = (const float4*)((p ? g_For : g_Fer) + m*4096);
    const float4* Fi4 = (const float4*)((p ? g_Foi : g_Fei) + m*4096);
    float4 ar = {0,0,0,0}, ai = {0,0,0,0};
    #pragma unroll 4
    for (int tt = 0; tt < 64; tt++) {
        float pv = Ps[li*64 + tt];
        float4 fr = Fr4[tt*16 + cq];
        float4 fi = Fi4[tt*16 + cq];
        ar += fr * pv;
        ai += fi * pv;
    }
    *(float4*)(g_flmr + (l*64 + m)*64 + cq*4) = ar;
    *(float4*)(g_flmi + (l*64 + m)*64 + cq*4) = ai;
}

// ---------------- complex spectral weight multiply (266 MB stream) -------
// 2 l per block: 16 independent LDG.128 per thread (__ldcs evict-first
// protects L2-resident scratch for downstream synl/ifin).
__global__ void k_wmul(const float* __restrict__ wr,
                       const float* __restrict__ wi) {
    int mf = blockIdx.x, l0 = blockIdx.y * 2;
    int tid = threadIdx.x;              // 256
    int og = tid & 15;
    int ig = tid >> 4;
    __shared__ float ar[2][64], ai[2][64];
    __shared__ float red[4][16][64];    // gr0, gi0, gr1, gi1
    if (tid < 128) {
        int ll = tid >> 6, i = tid & 63;
        int l = l0 + ll;
        float r, im;
        if (mf >= 63) {
            int m = mf - 63;
            r  = g_flmr[(l*64 + m)*64 + i];
            im = g_flmi[(l*64 + m)*64 + i];
        } else {
            int m = 63 - mf;
            float sgn = (m & 1) ? -1.f : 1.f;
            r  =  sgn * g_flmr[(l*64 + m)*64 + i];
            im = -sgn * g_flmi[(l*64 + m)*64 + i];
        }
        ar[ll][i] = r; ai[ll][i] = im;
    }
    __syncthreads();
    const float4* wr0 = (const float4*)(wr + (size_t)(l0*127 + mf)*4096);
    const float4* wi0 = (const float4*)(wi + (size_t)(l0*127 + mf)*4096);
    const float4* wr1 = (const float4*)(wr + (size_t)((l0+1)*127 + mf)*4096);
    const float4* wi1 = (const float4*)(wi + (size_t)((l0+1)*127 + mf)*4096);
    float4 gr0 = {0,0,0,0}, gi0 = {0,0,0,0}, gr1 = {0,0,0,0}, gi1 = {0,0,0,0};
    #pragma unroll
    for (int ii = 0; ii < 4; ii++) {
        int i = ig*4 + ii;
        float4 a0 = __ldcs(&wr0[i*16 + og]);
        float4 b0 = __ldcs(&wi0[i*16 + og]);
        float4 a1 = __ldcs(&wr1[i*16 + og]);
        float4 b1 = __ldcs(&wi1[i*16 + og]);
        float xr0 = ar[0][i], xi0 = ai[0][i];
        float xr1 = ar[1][i], xi1 = ai[1][i];
        gr0 += a0 * xr0;  gr0 -= b0 * xi0;
        gi0 += b0 * xr0;  gi0 += a0 * xi0;
        gr1 += a1 * xr1;  gr1 -= b1 * xi1;
        gi1 += b1 * xr1;  gi1 += a1 * xi1;
    }
    *(float4*)&red[0][ig][og*4] = gr0;
    *(float4*)&red[1][ig][og*4] = gi0;
    *(float4*)&red[2][ig][og*4] = gr1;
    *(float4*)&red[3][ig][og*4] = gi1;
    __syncthreads();
    if (tid < 128) {
        int ll = tid >> 6, o = tid & 63;
        float sr = 0.f, si = 0.f;
        #pragma unroll
        for (int g = 0; g < 16; g++) {
            sr += red[ll*2 + 0][g][o];
            si += red[ll*2 + 1][g][o];
        }
        g_glr[((l0 + ll)*127 + mf)*64 + o] = sr;
        g_gli[((l0 + ll)*127 + mf)*64 + o] = si;
    }
}

// ---------------- Legendre synthesis (theta-parity folded) ---------------
__global__ void k_synl(const float* __restrict__ P_out) {
    int mf = blockIdx.x;
    int m = (mf >= 63) ? (mf - 63) : (63 - mf);
    int tid = threadIdx.x;              // 256
    int og = tid & 15, tg = tid >> 4;   // t = tg*4+j, t < 64
    __shared__ float glsr[64*64], glsi[64*64];  // [l][o]
    __shared__ float Ps[64*64];                 // [l][t<64]
    for (int i = tid; i < 64*16; i += 256) {
        int l = i >> 4, f = i & 15;
        ((float4*)glsr)[i] = *(const float4*)(g_glr + (l*127 + mf)*64 + f*4);
        ((float4*)glsi)[i] = *(const float4*)(g_gli + (l*127 + mf)*64 + f*4);
        ((float4*)Ps)[i]   = *(const float4*)(P_out + (size_t)(l*127 + mf)*128 + f*4);
    }
    __syncthreads();
    float4 Ar[4], Ai[4], Br[4], Bi[4];
    #pragma unroll
    for (int j = 0; j < 4; j++) {
        Ar[j] = make_float4(0,0,0,0); Ai[j] = make_float4(0,0,0,0);
        Br[j] = make_float4(0,0,0,0); Bi[j] = make_float4(0,0,0,0);
    }
    int pA = m & 1;
    #pragma unroll 2
    for (int j2 = 0; j2 < 32; j2++) {
        int lA = pA + 2*j2, lB = (pA ^ 1) + 2*j2;
        float4 grA = ((float4*)glsr)[lA*16 + og];
        float4 giA = ((float4*)glsi)[lA*16 + og];
        float4 pAv = ((float4*)Ps)[lA*16 + tg];
        float4 grB = ((float4*)glsr)[lB*16 + og];
        float4 giB = ((float4*)glsi)[lB*16 + og];
        float4 pBv = ((float4*)Ps)[lB*16 + tg];
        Ar[0] += grA * pAv.x;  Ai[0] += giA * pAv.x;
        Ar[1] += grA * pAv.y;  Ai[1] += giA * pAv.y;
        Ar[2] += grA * pAv.z;  Ai[2] += giA * pAv.z;
        Ar[3] += grA * pAv.w;  Ai[3] += giA * pAv.w;
        Br[0] += grB * pBv.x;  Bi[0] += giB * pBv.x;
        Br[1] += grB * pBv.y;  Bi[1] += giB * pBv.y;
        Br[2] += grB * pBv.z;  Bi[2] += giB * pBv.z;
        Br[3] += grB * pBv.w;  Bi[3] += giB * pBv.w;
    }
    #pragma unroll
    for (int j = 0; j < 4; j++) {
        int t  = tg*4 + j;
        int t2 = 127 - t;
        *(float4*)(g_gr + (t *127 + mf)*64 + og*4) = Ar[j] + Br[j];
        *(float4*)(g_gi + (t *127 + mf)*64 + og*4) = Ai[j] + Bi[j];
        *(float4*)(g_gr + (t2*127 + mf)*64 + og*4) = Ar[j] - Br[j];
        *(float4*)(g_gi + (t2*127 + mf)*64 + og*4) = Ai[j] - Bi[j];
    }
}

// ---------------- fused inverse-longitude + conv + LN + ReLU -------------
__global__ void k_ifin(const float* __restrict__ x,
                       const float* __restrict__ ln_scale,
                       const float* __restrict__ ln_bias,
                       float* __restrict__ out) {
    int t = blockIdx.x;
    int tid = threadIdx.x;              // 320
    int og = tid & 15, kg = tid >> 4;   // kg 0..19; k' = kg*4+j
    bool act = (kg <= 16);
    __shared__ float GrS[8*64], GiS[8*64];
    __shared__ float cS[8*68], sS[8*68];
    __shared__ float xs[128*64];        // x_spec tile
    float4 A[4], B[4];
    #pragma unroll
    for (int j = 0; j < 4; j++) { A[j] = make_float4(0,0,0,0); B[j] = make_float4(0,0,0,0); }
    for (int ch = 0; ch < 8; ch++) {
        int mm0 = ch * 8;
        __syncthreads();
        for (int i = tid; i < 8*16; i += 320) {
            int mm = i >> 4, f = i & 15;
            int MM = mm0 + mm;
            float4 grv = *((const float4*)(g_gr + (t*127 + 63 + MM)*64) + f);
            float4 giv = *((const float4*)(g_gi + (t*127 + 63 + MM)*64) + f);
            if (MM) {
                grv += *((const float4*)(g_gr + (t*127 + 63 - MM)*64) + f);
                giv -= *((const float4*)(g_gi + (t*127 + 63 - MM)*64) + f);
            }
            ((float4*)GrS)[i] = grv;
            ((float4*)GiS)[i] = giv;
        }
        for (int i = tid; i < 8*17; i += 320) {
            int mm = i / 17, f = i % 17;
            ((float4*)cS)[i] = *(const float4*)(g_cE + (63 + mm0 + mm)*128 + f*4);
            ((float4*)sS)[i] = *(const float4*)(g_sE + (63 + mm0 + mm)*128 + f*4);
        }
        __syncthreads();
        if (act) {
            #pragma unroll
            for (int mm = 0; mm < 8; mm++) {
                float4 Gr = ((float4*)GrS)[mm*16 + og];
                float4 Gi = ((float4*)GiS)[mm*16 + og];
                float4 cv = *(float4*)&cS[mm*68 + kg*4];
                float4 sv = *(float4*)&sS[mm*68 + kg*4];
                A[0] += Gr * cv.x;  B[0] += Gi * sv.x;
                A[1] += Gr * cv.y;  B[1] += Gi * sv.y;
                A[2] += Gr * cv.z;  B[2] += Gi * sv.z;
                A[3] += Gr * cv.w;  B[3] += Gi * sv.w;
            }
        }
    }
    if (act) {
        #pragma unroll
        for (int j = 0; j < 4; j++) {
            int k = kg*4 + j;
            if (k <= 64) {
                *(float4*)&xs[k*64 + og*4] = A[j] - B[j];
                if (k >= 1 && k <= 63)
                    *(float4*)&xs[(128 - k)*64 + og*4] = A[j] + B[j];
            }
        }
    }
    __syncthreads();
    // ---- phase 2: conv-path scalar + LN + ReLU (first 8 warps) ----
    if (tid < 256) {
        int w = tid >> 5, lane = tid & 31;
        float cw1 = g_cw[lane],        cw2 = g_cw[lane + 32];
        float tv1 = g_tv[lane],        tv2 = g_tv[lane + 32];
        float bt1 = g_bt[lane],        bt2 = g_bt[lane + 32];
        float lns1 = ln_scale[lane],   lnb1 = ln_bias[lane];
        float lns2 = ln_scale[lane+32], lnb2 = ln_bias[lane+32];
        float cb = g_cb[0];
        for (int k = w; k < 128; k += 8) {
            const float* xp = x + (t*128 + k)*64;
            float x1 = xp[lane], x2 = xp[lane + 32];
            float S = x1*cw1 + x2*cw2;
            #pragma unroll
            for (int off = 16; off; off >>= 1)
                S += __shfl_xor_sync(0xffffffffu, S, off);
            S += cb;
            float v1 = xs[k*64 + lane]      + tv1*S + bt1;
            float v2 = xs[k*64 + lane + 32] + tv2*S + bt2;
            float s  = v1 + v2;
            float sq = v1*v1 + v2*v2;
            #pragma unroll
            for (int off = 16; off; off >>= 1) {
                s  += __shfl_xor_sync(0xffffffffu, s,  off);
                sq += __shfl_xor_sync(0xffffffffu, sq, off);
            }
            float mu   = s * (1.0f/64.0f);
            float var  = sq * (1.0f/64.0f) - mu*mu;
            float rstd = rsqrtf(var + 1e-6f);
            float r1 = (v1 - mu)*rstd*lns1 + lnb1;
            float r2 = (v2 - mu)*rstd*lns2 + lnb2;
            float* op = out + (t*128 + k)*64;
            op[lane]      = fmaxf(r1, 0.f);
            op[lane + 32] = fmaxf(r2, 0.f);
        }
    }
}

// ---------------- launch -------------------------------------------------
extern "C" void kernel_launch(void* const* d_in, const int* in_sizes, int n_in,
                              void* d_out, int out_size) {
    const float* x        = (const float*)d_in[0];
    const float* t_emb    = (const float*)d_in[1];
    const float* wr       = (const float*)d_in[2];
    const float* wi       = (const float*)d_in[3];
    const float* conv_w   = (const float*)d_in[4];
    const float* conv_b   = (const float*)d_in[5];
    const float* time_w   = (const float*)d_in[6];
    const float* dense_w  = (const float*)d_in[7];
    const float* ln_scale = (const float*)d_in[8];
    const float* ln_bias  = (const float*)d_in[9];
    const float* P_in     = (const float*)d_in[10];
    const float* P_out    = (const float*)d_in[11];
    const float* quad_w   = (const float*)d_in[12];
    float* out = (float*)d_out;

    k_dftp <<<dim3(64, 2), 512>>>(x, quad_w);
    k_setup<<<65, 256>>>(t_emb, dense_w, conv_w, conv_b, time_w);
    k_ana  <<<dim3(64, 4), 256>>>(P_in);
    k_wmul <<<dim3(127, 32), 256>>>(wr, wi);
    k_synl <<<127, 256>>>(P_out);
    k_ifin <<<128, 320>>>(x, ln_scale, ln_bias, out);
}

// round 16
// speedup vs baseline: 1.1693x; 1.0056x over previous
#include <cuda_runtime.h>
#include <math.h>

#define PI_F 3.14159265358979323846f

// ---- float4 helpers ----
__device__ __forceinline__ float4 operator+(float4 a, float4 b){ return make_float4(a.x+b.x,a.y+b.y,a.z+b.z,a.w+b.w); }
__device__ __forceinline__ float4 operator-(float4 a, float4 b){ return make_float4(a.x-b.x,a.y-b.y,a.z-b.z,a.w-b.w); }
__device__ __forceinline__ float4 operator*(float4 a, float s){ return make_float4(a.x*s,a.y*s,a.z*s,a.w*s); }
__device__ __forceinline__ void operator+=(float4& a, float4 b){ a.x+=b.x; a.y+=b.y; a.z+=b.z; a.w+=b.w; }
__device__ __forceinline__ void operator-=(float4& a, float4 b){ a.x-=b.x; a.y-=b.y; a.z-=b.z; a.w-=b.w; }

// ---------------- scratch ----------------
__device__ float g_Fer[64*64*64];    // parity-folded F: [m][t<64][c]
__device__ float g_Fei[64*64*64];
__device__ float g_For[64*64*64];
__device__ float g_Foi[64*64*64];
__device__ float g_flmr[64*64*64];   // [l][m][c]
__device__ float g_flmi[64*64*64];
__device__ float g_glr[64*127*64];   // [l][mf][o]
__device__ float g_gli[64*127*64];
__device__ float g_gr[128*127*64];   // [t][mf][o]
__device__ float g_gi[128*127*64];
__device__ float g_cE[127*128];      // [mf][k]
__device__ float g_sE[127*128];
__device__ float g_tv[64];
__device__ float g_bt[64];
__device__ float g_cw[64];
__device__ float g_cb[1];

// ---------------- setup: E twiddle table + time modulation ---------------
__global__ void k_setup(const float* __restrict__ t_emb,
                        const float* __restrict__ dense_w,
                        const float* __restrict__ conv_w,
                        const float* __restrict__ conv_b,
                        const float* __restrict__ time_w) {
    int bx = blockIdx.x;
    int tid = threadIdx.x;              // 256
    const float w0 = 2.0f * PI_F / 128.0f;
    if (bx < 64) {                      // E table [mf][k], 127*128
        int j = bx*256 + tid;
        if (j < 127*128) {
            int mf = j >> 7, k = j & 127;
            int m = mf - 63;
            int r = ((m * k) % 128 + 128) & 127;
            float s, c; sincosf(w0 * (float)r, &s, &c);
            g_cE[mf*128 + k] = c; g_sE[mf*128 + k] = s;
        }
    } else {                            // time modulation
        __shared__ float psum[256];
        __shared__ float psi[128];
        int j = tid >> 1, half = tid & 1;
        float s = 0.f;
        const float* dw = dense_w + half*128*128 + j;
        #pragma unroll 8
        for (int d = 0; d < 128; d++) s += t_emb[half*128 + d] * dw[d*128];
        psum[tid] = s;
        __syncthreads();
        if (tid < 128) psi[tid] = psum[2*tid] + psum[2*tid + 1];
        __syncthreads();
        if (tid < 64) {
            float tv = 0.f;
            for (int jj = 0; jj < 64; jj++) tv += time_w[tid*64 + jj] * psi[jj];
            g_tv[tid] = tv;
            g_bt[tid] = psi[64 + tid];
        } else if (tid < 128) {
            int c = tid - 64;
            float cs = 0.f;
            for (int o = 0; o < 64; o++) cs += conv_w[c*64 + o];
            g_cw[c] = cs;
        } else if (tid == 128) {
            float cb = 0.f;
            for (int o = 0; o < 64; o++) cb += conv_b[o];
            g_cb[0] = cb;
        }
    }
}

// ---------------- longitude DFT + theta-parity fold (fused) --------------
__global__ void k_dftp(const float* __restrict__ x,
                       const float* __restrict__ quad_w) {
    int tp = blockIdx.x;                // 0..63
    int c0 = blockIdx.y * 32;
    int tid = threadIdx.x;              // 512
    int cq = tid & 7, mg = tid >> 3;    // c = c0 + cq*4, m = mg (0..63)
    const float w0 = 2.0f * PI_F / 128.0f;
    __shared__ float xeA[64*32], xoA[64*32], xeB[64*32], xoB[64*32];
    __shared__ float tcs[16*64], tss[16*64];
    const float* xA = x + tp*8192 + c0;
    const float* xB = x + (127 - tp)*8192 + c0;
    for (int i = tid; i < 64*8; i += 512) {   // 64 n-rows x 8 float4
        int n = i >> 3, f = i & 7;
        if (n == 0) {
            ((float4*)xeA)[f] = *(const float4*)(xA + f*4);          // x[0]
            ((float4*)xoA)[f] = *(const float4*)(xA + 64*64 + f*4);  // x[64]
            ((float4*)xeB)[f] = *(const float4*)(xB + f*4);
            ((float4*)xoB)[f] = *(const float4*)(xB + 64*64 + f*4);
        } else {
            float4 a = *(const float4*)(xA + n*64 + f*4);
            float4 b = *(const float4*)(xA + (128 - n)*64 + f*4);
            ((float4*)xeA)[i] = a + b;
            ((float4*)xoA)[i] = a - b;
            a = *(const float4*)(xB + n*64 + f*4);
            b = *(const float4*)(xB + (128 - n)*64 + f*4);
            ((float4*)xeB)[i] = a + b;
            ((float4*)xoB)[i] = a - b;
        }
    }
    float4 arA = {0,0,0,0}, aiA = {0,0,0,0}, arB = {0,0,0,0}, aiB = {0,0,0,0};
    for (int ch = 0; ch < 4; ch++) {
        __syncthreads();
        for (int i = tid; i < 1024; i += 512) {   // twiddle chunk [16n][64m]
            int n = ch*16 + (i >> 6), m = i & 63;
            int r = (m * n) & 127;
            float s, c; sincosf(w0 * (float)r, &s, &c);
            tcs[i] = c; tss[i] = s;
        }
        __syncthreads();
        #pragma unroll 4
        for (int ln = 0; ln < 16; ln++) {
            int n = ch*16 + ln;
            if (n == 0) continue;
            float4 xeAv = ((float4*)xeA)[n*8 + cq];
            float4 xoAv = ((float4*)xoA)[n*8 + cq];
            float4 xeBv = ((float4*)xeB)[n*8 + cq];
            float4 xoBv = ((float4*)xoB)[n*8 + cq];
            float cv = tcs[ln*64 + mg];
            float sv = tss[ln*64 + mg];
            arA += xeAv * cv;  aiA -= xoAv * sv;
            arB += xeBv * cv;  aiB -= xoBv * sv;
        }
    }
    float sgn = (mg & 1) ? -1.f : 1.f;
    float4 x0A  = ((float4*)xeA)[cq], x64A = ((float4*)xoA)[cq];
    float4 x0B  = ((float4*)xeB)[cq], x64B = ((float4*)xoB)[cq];
    arA += x0A + x64A * sgn;
    arB += x0B + x64B * sgn;
    float sA = (2.0f * PI_F / 128.0f) * quad_w[tp];
    float sB = (2.0f * PI_F / 128.0f) * quad_w[127 - tp];
    float4 FrA = arA * sA, FiA = aiA * sA;
    float4 FrB = arB * sB, FiB = aiB * sB;
    int off = (mg*64 + tp)*64 + c0 + cq*4;
    *(float4*)(g_Fer + off) = FrA + FrB;
    *(float4*)(g_For + off) = FrA - FrB;
    *(float4*)(g_Fei + off) = FiA + FiB;
    *(float4*)(g_Foi + off) = FiA - FiB;
}

// ---------------- Legendre analysis (parity-halved) ----------------------
__global__ void k_ana(const float* __restrict__ P_in) {
    int m = blockIdx.x, l0 = blockIdx.y * 16;
    int tid = threadIdx.x;              // 256
    int cq = tid & 15, li = tid >> 4;
    int l = l0 + li;
    __shared__ float Ps[16*64];         // [li][t<64]
    for (int i = tid; i < 16*16; i += 256)
        ((float4*)Ps)[i] = *(const float4*)(P_in + (size_t)((l0 + (i >> 4))*127 + 63 + m)*128 + (i & 15)*4);
    __syncthreads();
    int p = (l + m) & 1;
    const float4* Fr4 = (const float4*)((p ? g_For : g_Fer) + m*4096);
    const float4* Fi4 = (const float4*)((p ? g_Foi : g_Fei) + m*4096);
    float4 ar = {0,0,0,0}, ai = {0,0,0,0};
    #pragma unroll 4
    for (int tt = 0; tt < 64; tt++) {
        float pv = Ps[li*64 + tt];
        float4 fr = Fr4[tt*16 + cq];
        float4 fi = Fi4[tt*16 + cq];
        ar += fr * pv;
        ai += fi * pv;
    }
    *(float4*)(g_flmr + (l*64 + m)*64 + cq*4) = ar;
    *(float4*)(g_flmi + (l*64 + m)*64 + cq*4) = ai;
}

// ---------------- complex spectral weight multiply (266 MB stream) -------
// 2 l per block: 16 independent LDG.128 per thread (__ldcs evict-first
// protects L2-resident scratch for downstream synl/ifin — measured).
__global__ void k_wmul(const float* __restrict__ wr,
                       const float* __restrict__ wi) {
    int mf = blockIdx.x, l0 = blockIdx.y * 2;
    int tid = threadIdx.x;              // 256
    int og = tid & 15;
    int ig = tid >> 4;
    __shared__ float ar[2][64], ai[2][64];
    __shared__ float red[4][16][64];    // gr0, gi0, gr1, gi1
    if (tid < 128) {
        int ll = tid >> 6, i = tid & 63;
        int l = l0 + ll;
        float r, im;
        if (mf >= 63) {
            int m = mf - 63;
            r  = g_flmr[(l*64 + m)*64 + i];
            im = g_flmi[(l*64 + m)*64 + i];
        } else {
            int m = 63 - mf;
            float sgn = (m & 1) ? -1.f : 1.f;
            r  =  sgn * g_flmr[(l*64 + m)*64 + i];
            im = -sgn * g_flmi[(l*64 + m)*64 + i];
        }
        ar[ll][i] = r; ai[ll][i] = im;
    }
    __syncthreads();
    const float4* wr0 = (const float4*)(wr + (size_t)(l0*127 + mf)*4096);
    const float4* wi0 = (const float4*)(wi + (size_t)(l0*127 + mf)*4096);
    const float4* wr1 = (const float4*)(wr + (size_t)((l0+1)*127 + mf)*4096);
    const float4* wi1 = (const float4*)(wi + (size_t)((l0+1)*127 + mf)*4096);
    float4 gr0 = {0,0,0,0}, gi0 = {0,0,0,0}, gr1 = {0,0,0,0}, gi1 = {0,0,0,0};
    #pragma unroll
    for (int ii = 0; ii < 4; ii++) {
        int i = ig*4 + ii;
        float4 a0 = __ldcs(&wr0[i*16 + og]);
        float4 b0 = __ldcs(&wi0[i*16 + og]);
        float4 a1 = __ldcs(&wr1[i*16 + og]);
        float4 b1 = __ldcs(&wi1[i*16 + og]);
        float xr0 = ar[0][i], xi0 = ai[0][i];
        float xr1 = ar[1][i], xi1 = ai[1][i];
        gr0 += a0 * xr0;  gr0 -= b0 * xi0;
        gi0 += b0 * xr0;  gi0 += a0 * xi0;
        gr1 += a1 * xr1;  gr1 -= b1 * xi1;
        gi1 += b1 * xr1;  gi1 += a1 * xi1;
    }
    *(float4*)&red[0][ig][og*4] = gr0;
    *(float4*)&red[1][ig][og*4] = gi0;
    *(float4*)&red[2][ig][og*4] = gr1;
    *(float4*)&red[3][ig][og*4] = gi1;
    __syncthreads();
    if (tid < 128) {
        int ll = tid >> 6, o = tid & 63;
        float sr = 0.f, si = 0.f;
        #pragma unroll
        for (int g = 0; g < 16; g++) {
            sr += red[ll*2 + 0][g][o];
            si += red[ll*2 + 1][g][o];
        }
        g_glr[((l0 + ll)*127 + mf)*64 + o] = sr;
        g_gli[((l0 + ll)*127 + mf)*64 + o] = si;
    }
}

// ---------------- Legendre synthesis (theta-parity folded) ---------------
// Same staging as champion; 512 threads (2 t per thread, 16 warps/SM).
__global__ void k_synl(const float* __restrict__ P_out) {
    int mf = blockIdx.x;
    int m = (mf >= 63) ? (mf - 63) : (63 - mf);
    int tid = threadIdx.x;              // 512
    int og = tid & 15, tg = tid >> 4;   // og: o-quad (16), tg: t-pair (32)
    __shared__ float glsr[64*64], glsi[64*64];  // [l][o]
    __shared__ float Ps[64*64];                 // [l][t<64]
    for (int i = tid; i < 64*16; i += 512) {
        int l = i >> 4, f = i & 15;
        ((float4*)glsr)[i] = *(const float4*)(g_glr + (l*127 + mf)*64 + f*4);
        ((float4*)glsi)[i] = *(const float4*)(g_gli + (l*127 + mf)*64 + f*4);
        ((float4*)Ps)[i]   = *(const float4*)(P_out + (size_t)(l*127 + mf)*128 + f*4);
    }
    __syncthreads();
    float4 Ar[2], Ai[2], Br[2], Bi[2];
    #pragma unroll
    for (int j = 0; j < 2; j++) {
        Ar[j] = make_float4(0,0,0,0); Ai[j] = make_float4(0,0,0,0);
        Br[j] = make_float4(0,0,0,0); Bi[j] = make_float4(0,0,0,0);
    }
    int pA = m & 1;
    #pragma unroll 4
    for (int j2 = 0; j2 < 32; j2++) {
        int lA = pA + 2*j2, lB = (pA ^ 1) + 2*j2;
        float4 grA = ((float4*)glsr)[lA*16 + og];
        float4 giA = ((float4*)glsi)[lA*16 + og];
        float2 pAv = *(float2*)&Ps[lA*64 + tg*2];
        float4 grB = ((float4*)glsr)[lB*16 + og];
        float4 giB = ((float4*)glsi)[lB*16 + og];
        float2 pBv = *(float2*)&Ps[lB*64 + tg*2];
        Ar[0] += grA * pAv.x;  Ai[0] += giA * pAv.x;
        Ar[1] += grA * pAv.y;  Ai[1] += giA * pAv.y;
        Br[0] += grB * pBv.x;  Bi[0] += giB * pBv.x;
        Br[1] += grB * pBv.y;  Bi[1] += giB * pBv.y;
    }
    #pragma unroll
    for (int j = 0; j < 2; j++) {
        int t  = tg*2 + j;
        int t2 = 127 - t;
        *(float4*)(g_gr + (t *127 + mf)*64 + og*4) = Ar[j] + Br[j];
        *(float4*)(g_gi + (t *127 + mf)*64 + og*4) = Ai[j] + Bi[j];
        *(float4*)(g_gr + (t2*127 + mf)*64 + og*4) = Ar[j] - Br[j];
        *(float4*)(g_gi + (t2*127 + mf)*64 + og*4) = Ai[j] - Bi[j];
    }
}

// ---------------- fused inverse-longitude + conv + LN + ReLU -------------
__global__ void k_ifin(const float* __restrict__ x,
                       const float* __restrict__ ln_scale,
                       const float* __restrict__ ln_bias,
                       float* __restrict__ out) {
    int t = blockIdx.x;
    int tid = threadIdx.x;              // 320
    int og = tid & 15, kg = tid >> 4;   // kg 0..19; k' = kg*4+j
    bool act = (kg <= 16);
    __shared__ float GrS[8*64], GiS[8*64];
    __shared__ float cS[8*68], sS[8*68];
    __shared__ float xs[128*64];        // x_spec tile
    float4 A[4], B[4];
    #pragma unroll
    for (int j = 0; j < 4; j++) { A[j] = make_float4(0,0,0,0); B[j] = make_float4(0,0,0,0); }
    for (int ch = 0; ch < 8; ch++) {
        int mm0 = ch * 8;
        __syncthreads();
        for (int i = tid; i < 8*16; i += 320) {
            int mm = i >> 4, f = i & 15;
            int MM = mm0 + mm;
            float4 grv = *((const float4*)(g_gr + (t*127 + 63 + MM)*64) + f);
            float4 giv = *((const float4*)(g_gi + (t*127 + 63 + MM)*64) + f);
            if (MM) {
                grv += *((const float4*)(g_gr + (t*127 + 63 - MM)*64) + f);
                giv -= *((const float4*)(g_gi + (t*127 + 63 - MM)*64) + f);
            }
            ((float4*)GrS)[i] = grv;
            ((float4*)GiS)[i] = giv;
        }
        for (int i = tid; i < 8*17; i += 320) {
            int mm = i / 17, f = i % 17;
            ((float4*)cS)[i] = *(const float4*)(g_cE + (63 + mm0 + mm)*128 + f*4);
            ((float4*)sS)[i] = *(const float4*)(g_sE + (63 + mm0 + mm)*128 + f*4);
        }
        __syncthreads();
        if (act) {
            #pragma unroll
            for (int mm = 0; mm < 8; mm++) {
                float4 Gr = ((float4*)GrS)[mm*16 + og];
                float4 Gi = ((float4*)GiS)[mm*16 + og];
                float4 cv = *(float4*)&cS[mm*68 + kg*4];
                float4 sv = *(float4*)&sS[mm*68 + kg*4];
                A[0] += Gr * cv.x;  B[0] += Gi * sv.x;
                A[1] += Gr * cv.y;  B[1] += Gi * sv.y;
                A[2] += Gr * cv.z;  B[2] += Gi * sv.z;
                A[3] += Gr * cv.w;  B[3] += Gi * sv.w;
            }
        }
    }
    if (act) {
        #pragma unroll
        for (int j = 0; j < 4; j++) {
            int k = kg*4 + j;
            if (k <= 64) {
                *(float4*)&xs[k*64 + og*4] = A[j] - B[j];
                if (k >= 1 && k <= 63)
                    *(float4*)&xs[(128 - k)*64 + og*4] = A[j] + B[j];
            }
        }
    }
    __syncthreads();
    // ---- phase 2: conv-path scalar + LN + ReLU (all 10 warps) ----
    {
        int w = tid >> 5, lane = tid & 31;
        float cw1 = g_cw[lane],        cw2 = g_cw[lane + 32];
        float tv1 = g_tv[lane],        tv2 = g_tv[lane + 32];
        float bt1 = g_bt[lane],        bt2 = g_bt[lane + 32];
        float lns1 = ln_scale[lane],   lnb1 = ln_bias[lane];
        float lns2 = ln_scale[lane+32], lnb2 = ln_bias[lane+32];
        float cb = g_cb[0];
        for (int k = w; k < 128; k += 10) {
            const float* xp = x + (t*128 + k)*64;
            float x1 = xp[lane], x2 = xp[lane + 32];
            float S = x1*cw1 + x2*cw2;
            #pragma unroll
            for (int off = 16; off; off >>= 1)
                S += __shfl_xor_sync(0xffffffffu, S, off);
            S += cb;
            float v1 = xs[k*64 + lane]      + tv1*S + bt1;
            float v2 = xs[k*64 + lane + 32] + tv2*S + bt2;
            float s  = v1 + v2;
            float sq = v1*v1 + v2*v2;
            #pragma unroll
            for (int off = 16; off; off >>= 1) {
                s  += __shfl_xor_sync(0xffffffffu, s,  off);
                sq += __shfl_xor_sync(0xffffffffu, sq, off);
            }
            float mu   = s * (1.0f/64.0f);
            float var  = sq * (1.0f/64.0f) - mu*mu;
            float rstd = rsqrtf(var + 1e-6f);
            float r1 = (v1 - mu)*rstd*lns1 + lnb1;
            float r2 = (v2 - mu)*rstd*lns2 + lnb2;
            float* op = out + (t*128 + k)*64;
            op[lane]      = fmaxf(r1, 0.f);
            op[lane + 32] = fmaxf(r2, 0.f);
        }
    }
}

// ---------------- launch -------------------------------------------------
extern "C" void kernel_launch(void* const* d_in, const int* in_sizes, int n_in,
                              void* d_out, int out_size) {
    const float* x        = (const float*)d_in[0];
    const float* t_emb    = (const float*)d_in[1];
    const float* wr       = (const float*)d_in[2];
    const float* wi       = (const float*)d_in[3];
    const float* conv_w   = (const float*)d_in[4];
    const float* conv_b   = (const float*)d_in[5];
    const float* time_w   = (const float*)d_in[6];
    const float* dense_w  = (const float*)d_in[7];
    const float* ln_scale = (const float*)d_in[8];
    const float* ln_bias  = (const float*)d_in[9];
    const float* P_in     = (const float*)d_in[10];
    const float* P_out    = (const float*)d_in[11];
    const float* quad_w   = (const float*)d_in[12];
    float* out = (float*)d_out;

    k_dftp <<<dim3(64, 2), 512>>>(x, quad_w);
    k_setup<<<65, 256>>>(t_emb, dense_w, conv_w, conv_b, time_w);
    k_ana  <<<dim3(64, 4), 256>>>(P_in);
    k_wmul <<<dim3(127, 32), 256>>>(wr, wi);
    k_synl <<<127, 512>>>(P_out);
    k_ifin <<<128, 320>>>(x, ln_scale, ln_bias, out);
}

// round 17
// speedup vs baseline: 1.3043x; 1.1154x over previous
#include <cuda_runtime.h>
#include <math.h>

#define PI_F 3.14159265358979323846f

// ---- float4 helpers ----
__device__ __forceinline__ float4 operator+(float4 a, float4 b){ return make_float4(a.x+b.x,a.y+b.y,a.z+b.z,a.w+b.w); }
__device__ __forceinline__ float4 operator-(float4 a, float4 b){ return make_float4(a.x-b.x,a.y-b.y,a.z-b.z,a.w-b.w); }
__device__ __forceinline__ float4 operator*(float4 a, float s){ return make_float4(a.x*s,a.y*s,a.z*s,a.w*s); }
__device__ __forceinline__ void operator+=(float4& a, float4 b){ a.x+=b.x; a.y+=b.y; a.z+=b.z; a.w+=b.w; }
__device__ __forceinline__ void operator-=(float4& a, float4 b){ a.x-=b.x; a.y-=b.y; a.z-=b.z; a.w-=b.w; }

// ---------------- scratch ----------------
__device__ float g_Fer[64*64*64];    // parity-folded F: [m][t<64][c]
__device__ float g_Fei[64*64*64];
__device__ float g_For[64*64*64];
__device__ float g_Foi[64*64*64];
__device__ float g_flmr[64*64*64];   // [l][m][c]
__device__ float g_flmi[64*64*64];
__device__ float g_glr[64*127*64];   // [l][mf][o]
__device__ float g_gli[64*127*64];
__device__ float g_gr[128*127*64];   // [t][mf][o]
__device__ float g_gi[128*127*64];
__device__ float g_tv[64];
__device__ float g_bt[64];
__device__ float g_cw[64];
__device__ float g_cb[1];

// ---------------- longitude DFT + theta-parity fold (fused) --------------
__global__ void k_dftp(const float* __restrict__ x,
                       const float* __restrict__ quad_w) {
    int tp = blockIdx.x;                // 0..63
    int c0 = blockIdx.y * 32;
    int tid = threadIdx.x;              // 512
    int cq = tid & 7, mg = tid >> 3;    // c = c0 + cq*4, m = mg (0..63)
    const float w0 = 2.0f * PI_F / 128.0f;
    __shared__ float xeA[64*32], xoA[64*32], xeB[64*32], xoB[64*32];
    __shared__ float tcs[16*64], tss[16*64];
    const float* xA = x + tp*8192 + c0;
    const float* xB = x + (127 - tp)*8192 + c0;
    for (int i = tid; i < 64*8; i += 512) {   // 64 n-rows x 8 float4
        int n = i >> 3, f = i & 7;
        if (n == 0) {
            ((float4*)xeA)[f] = *(const float4*)(xA + f*4);          // x[0]
            ((float4*)xoA)[f] = *(const float4*)(xA + 64*64 + f*4);  // x[64]
            ((float4*)xeB)[f] = *(const float4*)(xB + f*4);
            ((float4*)xoB)[f] = *(const float4*)(xB + 64*64 + f*4);
        } else {
            float4 a = *(const float4*)(xA + n*64 + f*4);
            float4 b = *(const float4*)(xA + (128 - n)*64 + f*4);
            ((float4*)xeA)[i] = a + b;
            ((float4*)xoA)[i] = a - b;
            a = *(const float4*)(xB + n*64 + f*4);
            b = *(const float4*)(xB + (128 - n)*64 + f*4);
            ((float4*)xeB)[i] = a + b;
            ((float4*)xoB)[i] = a - b;
        }
    }
    float4 arA = {0,0,0,0}, aiA = {0,0,0,0}, arB = {0,0,0,0}, aiB = {0,0,0,0};
    for (int ch = 0; ch < 4; ch++) {
        __syncthreads();
        for (int i = tid; i < 1024; i += 512) {   // twiddle chunk [16n][64m]
            int n = ch*16 + (i >> 6), m = i & 63;
            int r = (m * n) & 127;
            float s, c; sincosf(w0 * (float)r, &s, &c);
            tcs[i] = c; tss[i] = s;
        }
        __syncthreads();
        #pragma unroll 4
        for (int ln = 0; ln < 16; ln++) {
            int n = ch*16 + ln;
            if (n == 0) continue;
            float4 xeAv = ((float4*)xeA)[n*8 + cq];
            float4 xoAv = ((float4*)xoA)[n*8 + cq];
            float4 xeBv = ((float4*)xeB)[n*8 + cq];
            float4 xoBv = ((float4*)xoB)[n*8 + cq];
            float cv = tcs[ln*64 + mg];
            float sv = tss[ln*64 + mg];
            arA += xeAv * cv;  aiA -= xoAv * sv;
            arB += xeBv * cv;  aiB -= xoBv * sv;
        }
    }
    float sgn = (mg & 1) ? -1.f : 1.f;
    float4 x0A  = ((float4*)xeA)[cq], x64A = ((float4*)xoA)[cq];
    float4 x0B  = ((float4*)xeB)[cq], x64B = ((float4*)xoB)[cq];
    arA += x0A + x64A * sgn;
    arB += x0B + x64B * sgn;
    float sA = (2.0f * PI_F / 128.0f) * quad_w[tp];
    float sB = (2.0f * PI_F / 128.0f) * quad_w[127 - tp];
    float4 FrA = arA * sA, FiA = aiA * sA;
    float4 FrB = arB * sB, FiB = aiB * sB;
    int off = (mg*64 + tp)*64 + c0 + cq*4;
    *(float4*)(g_Fer + off) = FrA + FrB;
    *(float4*)(g_For + off) = FrA - FrB;
    *(float4*)(g_Fei + off) = FiA + FiB;
    *(float4*)(g_Foi + off) = FiA - FiB;
}

// ---------------- Legendre analysis (parity-halved) + modulation ---------
// bx < 64: analysis for m = bx. bx == 64 (y == 0 only): time modulation.
__global__ void k_ana(const float* __restrict__ P_in,
                      const float* __restrict__ t_emb,
                      const float* __restrict__ dense_w,
                      const float* __restrict__ conv_w,
                      const float* __restrict__ conv_b,
                      const float* __restrict__ time_w) {
    int tid = threadIdx.x;              // 256
    if (blockIdx.x == 64) {
        if (blockIdx.y != 0) return;
        __shared__ float psum[256];
        __shared__ float psi[128];
        int j = tid >> 1, half = tid & 1;
        float s = 0.f;
        const float* dw = dense_w + half*128*128 + j;
        #pragma unroll 8
        for (int d = 0; d < 128; d++) s += t_emb[half*128 + d] * dw[d*128];
        psum[tid] = s;
        __syncthreads();
        if (tid < 128) psi[tid] = psum[2*tid] + psum[2*tid + 1];
        __syncthreads();
        if (tid < 64) {
            float tv = 0.f;
            for (int jj = 0; jj < 64; jj++) tv += time_w[tid*64 + jj] * psi[jj];
            g_tv[tid] = tv;
            g_bt[tid] = psi[64 + tid];
        } else if (tid < 128) {
            int c = tid - 64;
            float cs = 0.f;
            for (int o = 0; o < 64; o++) cs += conv_w[c*64 + o];
            g_cw[c] = cs;
        } else if (tid == 128) {
            float cb = 0.f;
            for (int o = 0; o < 64; o++) cb += conv_b[o];
            g_cb[0] = cb;
        }
        return;
    }
    int m = blockIdx.x, l0 = blockIdx.y * 16;
    int cq = tid & 15, li = tid >> 4;
    int l = l0 + li;
    __shared__ float Ps[16*64];         // [li][t<64]
    for (int i = tid; i < 16*16; i += 256)
        ((float4*)Ps)[i] = *(const float4*)(P_in + (size_t)((l0 + (i >> 4))*127 + 63 + m)*128 + (i & 15)*4);
    __syncthreads();
    int p = (l + m) & 1;
    const float4* Fr4 = (const float4*)((p ? g_For : g_Fer) + m*4096);
    const float4* Fi4 = (const float4*)((p ? g_Foi : g_Fei) + m*4096);
    float4 ar = {0,0,0,0}, ai = {0,0,0,0};
    #pragma unroll 4
    for (int tt = 0; tt < 64; tt++) {
        float pv = Ps[li*64 + tt];
        float4 fr = Fr4[tt*16 + cq];
        float4 fi = Fi4[tt*16 + cq];
        ar += fr * pv;
        ai += fi * pv;
    }
    *(float4*)(g_flmr + (l*64 + m)*64 + cq*4) = ar;
    *(float4*)(g_flmi + (l*64 + m)*64 + cq*4) = ai;
}

// ---------------- complex spectral weight multiply (266 MB stream) -------
// 2 l per block: 16 independent LDG.128 per thread (__ldcs evict-first
// protects L2-resident scratch for downstream synl/ifin — measured).
__global__ void k_wmul(const float* __restrict__ wr,
                       const float* __restrict__ wi) {
    int mf = blockIdx.x, l0 = blockIdx.y * 2;
    int tid = threadIdx.x;              // 256
    int og = tid & 15;
    int ig = tid >> 4;
    __shared__ float ar[2][64], ai[2][64];
    __shared__ float red[4][16][64];    // gr0, gi0, gr1, gi1
    if (tid < 128) {
        int ll = tid >> 6, i = tid & 63;
        int l = l0 + ll;
        float r, im;
        if (mf >= 63) {
            int m = mf - 63;
            r  = g_flmr[(l*64 + m)*64 + i];
            im = g_flmi[(l*64 + m)*64 + i];
        } else {
            int m = 63 - mf;
            float sgn = (m & 1) ? -1.f : 1.f;
            r  =  sgn * g_flmr[(l*64 + m)*64 + i];
            im = -sgn * g_flmi[(l*64 + m)*64 + i];
        }
        ar[ll][i] = r; ai[ll][i] = im;
    }
    __syncthreads();
    const float4* wr0 = (const float4*)(wr + (size_t)(l0*127 + mf)*4096);
    const float4* wi0 = (const float4*)(wi + (size_t)(l0*127 + mf)*4096);
    const float4* wr1 = (const float4*)(wr + (size_t)((l0+1)*127 + mf)*4096);
    const float4* wi1 = (const float4*)(wi + (size_t)((l0+1)*127 + mf)*4096);
    float4 gr0 = {0,0,0,0}, gi0 = {0,0,0,0}, gr1 = {0,0,0,0}, gi1 = {0,0,0,0};
    #pragma unroll
    for (int ii = 0; ii < 4; ii++) {
        int i = ig*4 + ii;
        float4 a0 = __ldcs(&wr0[i*16 + og]);
        float4 b0 = __ldcs(&wi0[i*16 + og]);
        float4 a1 = __ldcs(&wr1[i*16 + og]);
        float4 b1 = __ldcs(&wi1[i*16 + og]);
        float xr0 = ar[0][i], xi0 = ai[0][i];
        float xr1 = ar[1][i], xi1 = ai[1][i];
        gr0 += a0 * xr0;  gr0 -= b0 * xi0;
        gi0 += b0 * xr0;  gi0 += a0 * xi0;
        gr1 += a1 * xr1;  gr1 -= b1 * xi1;
        gi1 += b1 * xr1;  gi1 += a1 * xi1;
    }
    *(float4*)&red[0][ig][og*4] = gr0;
    *(float4*)&red[1][ig][og*4] = gi0;
    *(float4*)&red[2][ig][og*4] = gr1;
    *(float4*)&red[3][ig][og*4] = gi1;
    __syncthreads();
    if (tid < 128) {
        int ll = tid >> 6, o = tid & 63;
        float sr = 0.f, si = 0.f;
        #pragma unroll
        for (int g = 0; g < 16; g++) {
            sr += red[ll*2 + 0][g][o];
            si += red[ll*2 + 1][g][o];
        }
        g_glr[((l0 + ll)*127 + mf)*64 + o] = sr;
        g_gli[((l0 + ll)*127 + mf)*64 + o] = si;
    }
}

// ---------------- Legendre synthesis (theta-parity folded) ---------------
__global__ void k_synl(const float* __restrict__ P_out) {
    int mf = blockIdx.x;
    int m = (mf >= 63) ? (mf - 63) : (63 - mf);
    int tid = threadIdx.x;              // 512
    int og = tid & 15, tg = tid >> 4;   // og: o-quad (16), tg: t-pair (32)
    __shared__ float glsr[64*64], glsi[64*64];  // [l][o]
    __shared__ float Ps[64*64];                 // [l][t<64]
    for (int i = tid; i < 64*16; i += 512) {
        int l = i >> 4, f = i & 15;
        ((float4*)glsr)[i] = *(const float4*)(g_glr + (l*127 + mf)*64 + f*4);
        ((float4*)glsi)[i] = *(const float4*)(g_gli + (l*127 + mf)*64 + f*4);
        ((float4*)Ps)[i]   = *(const float4*)(P_out + (size_t)(l*127 + mf)*128 + f*4);
    }
    __syncthreads();
    float4 Ar[2], Ai[2], Br[2], Bi[2];
    #pragma unroll
    for (int j = 0; j < 2; j++) {
        Ar[j] = make_float4(0,0,0,0); Ai[j] = make_float4(0,0,0,0);
        Br[j] = make_float4(0,0,0,0); Bi[j] = make_float4(0,0,0,0);
    }
    int pA = m & 1;
    #pragma unroll 4
    for (int j2 = 0; j2 < 32; j2++) {
        int lA = pA + 2*j2, lB = (pA ^ 1) + 2*j2;
        float4 grA = ((float4*)glsr)[lA*16 + og];
        float4 giA = ((float4*)glsi)[lA*16 + og];
        float2 pAv = *(float2*)&Ps[lA*64 + tg*2];
        float4 grB = ((float4*)glsr)[lB*16 + og];
        float4 giB = ((float4*)glsi)[lB*16 + og];
        float2 pBv = *(float2*)&Ps[lB*64 + tg*2];
        Ar[0] += grA * pAv.x;  Ai[0] += giA * pAv.x;
        Ar[1] += grA * pAv.y;  Ai[1] += giA * pAv.y;
        Br[0] += grB * pBv.x;  Bi[0] += giB * pBv.x;
        Br[1] += grB * pBv.y;  Bi[1] += giB * pBv.y;
    }
    #pragma unroll
    for (int j = 0; j < 2; j++) {
        int t  = tg*2 + j;
        int t2 = 127 - t;
        *(float4*)(g_gr + (t *127 + mf)*64 + og*4) = Ar[j] + Br[j];
        *(float4*)(g_gi + (t *127 + mf)*64 + og*4) = Ai[j] + Bi[j];
        *(float4*)(g_gr + (t2*127 + mf)*64 + og*4) = Ar[j] - Br[j];
        *(float4*)(g_gi + (t2*127 + mf)*64 + og*4) = Ai[j] - Bi[j];
    }
}

// ---------------- fused inverse-longitude + conv + LN + ReLU -------------
// E twiddles computed inline (exact integer mod-128 + sincosf; no table).
__global__ void k_ifin(const float* __restrict__ x,
                       const float* __restrict__ ln_scale,
                       const float* __restrict__ ln_bias,
                       float* __restrict__ out) {
    int t = blockIdx.x;
    int tid = threadIdx.x;              // 320
    int og = tid & 15, kg = tid >> 4;   // kg 0..19; k' = kg*4+j
    bool act = (kg <= 16);
    const float w0 = 2.0f * PI_F / 128.0f;
    __shared__ float GrS[8*64], GiS[8*64];
    __shared__ float cS[8*68], sS[8*68];
    __shared__ float xs[128*64];        // x_spec tile
    float4 A[4], B[4];
    #pragma unroll
    for (int j = 0; j < 4; j++) { A[j] = make_float4(0,0,0,0); B[j] = make_float4(0,0,0,0); }
    for (int ch = 0; ch < 8; ch++) {
        int mm0 = ch * 8;
        __syncthreads();
        for (int i = tid; i < 8*16; i += 320) {
            int mm = i >> 4, f = i & 15;
            int MM = mm0 + mm;
            float4 grv = *((const float4*)(g_gr + (t*127 + 63 + MM)*64) + f);
            float4 giv = *((const float4*)(g_gi + (t*127 + 63 + MM)*64) + f);
            if (MM) {
                grv += *((const float4*)(g_gr + (t*127 + 63 - MM)*64) + f);
                giv -= *((const float4*)(g_gi + (t*127 + 63 - MM)*64) + f);
            }
            ((float4*)GrS)[i] = grv;
            ((float4*)GiS)[i] = giv;
        }
        for (int i = tid; i < 8*17; i += 320) {
            int mm = i / 17, f = i % 17;   // row m = mm0+mm; cols k = f*4..f*4+3
            int MM = mm0 + mm;
            float4 cv, sv;
            {
                int k0 = f*4;
                int r0 = (MM * (k0+0)) & 127;
                int r1 = (MM * (k0+1)) & 127;
                int r2 = (MM * (k0+2)) & 127;
                int r3 = (MM * (k0+3)) & 127;
                sincosf(w0 * (float)r0, &sv.x, &cv.x);
                sincosf(w0 * (float)r1, &sv.y, &cv.y);
                sincosf(w0 * (float)r2, &sv.z, &cv.z);
                sincosf(w0 * (float)r3, &sv.w, &cv.w);
            }
            *(float4*)&cS[mm*68 + f*4] = cv;
            *(float4*)&sS[mm*68 + f*4] = sv;
        }
        __syncthreads();
        if (act) {
            #pragma unroll
            for (int mm = 0; mm < 8; mm++) {
                float4 Gr = ((float4*)GrS)[mm*16 + og];
                float4 Gi = ((float4*)GiS)[mm*16 + og];
                float4 cv = *(float4*)&cS[mm*68 + kg*4];
                float4 sv = *(float4*)&sS[mm*68 + kg*4];
                A[0] += Gr * cv.x;  B[0] += Gi * sv.x;
                A[1] += Gr * cv.y;  B[1] += Gi * sv.y;
                A[2] += Gr * cv.z;  B[2] += Gi * sv.z;
                A[3] += Gr * cv.w;  B[3] += Gi * sv.w;
            }
        }
    }
    if (act) {
        #pragma unroll
        for (int j = 0; j < 4; j++) {
            int k = kg*4 + j;
            if (k <= 64) {
                *(float4*)&xs[k*64 + og*4] = A[j] - B[j];
                if (k >= 1 && k <= 63)
                    *(float4*)&xs[(128 - k)*64 + og*4] = A[j] + B[j];
            }
        }
    }
    __syncthreads();
    // ---- phase 2: conv-path scalar + LN + ReLU (all 10 warps) ----
    {
        int w = tid >> 5, lane = tid & 31;
        float cw1 = g_cw[lane],        cw2 = g_cw[lane + 32];
        float tv1 = g_tv[lane],        tv2 = g_tv[lane + 32];
        float bt1 = g_bt[lane],        bt2 = g_bt[lane + 32];
        float lns1 = ln_scale[lane],   lnb1 = ln_bias[lane];
        float lns2 = ln_scale[lane+32], lnb2 = ln_bias[lane+32];
        float cb = g_cb[0];
        for (int k = w; k < 128; k += 10) {
            const float* xp = x + (t*128 + k)*64;
            float x1 = xp[lane], x2 = xp[lane + 32];
            float S = x1*cw1 + x2*cw2;
            #pragma unroll
            for (int off = 16; off; off >>= 1)
                S += __shfl_xor_sync(0xffffffffu, S, off);
            S += cb;
            float v1 = xs[k*64 + lane]      + tv1*S + bt1;
            float v2 = xs[k*64 + lane + 32] + tv2*S + bt2;
            float s  = v1 + v2;
            float sq = v1*v1 + v2*v2;
            #pragma unroll
            for (int off = 16; off; off >>= 1) {
                s  += __shfl_xor_sync(0xffffffffu, s,  off);
                sq += __shfl_xor_sync(0xffffffffu, sq, off);
            }
            float mu   = s * (1.0f/64.0f);
            float var  = sq * (1.0f/64.0f) - mu*mu;
            float rstd = rsqrtf(var + 1e-6f);
            float r1 = (v1 - mu)*rstd*lns1 + lnb1;
            float r2 = (v2 - mu)*rstd*lns2 + lnb2;
            float* op = out + (t*128 + k)*64;
            op[lane]      = fmaxf(r1, 0.f);
            op[lane + 32] = fmaxf(r2, 0.f);
        }
    }
}

// ---------------- launch -------------------------------------------------
extern "C" void kernel_launch(void* const* d_in, const int* in_sizes, int n_in,
                              void* d_out, int out_size) {
    const float* x        = (const float*)d_in[0];
    const float* t_emb    = (const float*)d_in[1];
    const float* wr       = (const float*)d_in[2];
    const float* wi       = (const float*)d_in[3];
    const float* conv_w   = (const float*)d_in[4];
    const float* conv_b   = (const float*)d_in[5];
    const float* time_w   = (const float*)d_in[6];
    const float* dense_w  = (const float*)d_in[7];
    const float* ln_scale = (const float*)d_in[8];
    const float* ln_bias  = (const float*)d_in[9];
    const float* P_in     = (const float*)d_in[10];
    const float* P_out    = (const float*)d_in[11];
    const float* quad_w   = (const float*)d_in[12];
    float* out = (float*)d_out;

    k_dftp <<<dim3(64, 2), 512>>>(x, quad_w);
    k_ana  <<<dim3(65, 4), 256>>>(P_in, t_emb, dense_w, conv_w, conv_b, time_w);
    k_wmul <<<dim3(127, 32), 256>>>(wr, wi);
    k_synl <<<127, 512>>>(P_out);
    k_ifin <<<128, 320>>>(x, ln_scale, ln_bias, out);
}